// round 17
// baseline (speedup 1.0000x reference)
#include <cuda_runtime.h>
#include <cuda_fp16.h>
#include <math.h>
#include <stdint.h>

// Problem constants
#define BATCH 4
#define SEQ   2048
#define DMODEL 1024
#define NHEAD 16
#define DHEAD 64
#define BM    (BATCH*SEQ)     // 8192
#define QKVS  3072            // fused QKV row stride

// ---------------- scratch (__device__ globals) ------------------------------
__device__ __half g_A   [BM*DMODEL];        // H fp16
__device__ __half g_W   [4*DMODEL*DMODEL];  // Wq,Wk,Wv,Wo fp16 (concat)
__device__ float  g_bias[QKVS];             // bq|bk|bv
__device__ __half g_AO  [BM*DMODEL];        // attention out fp16 (ORIGINAL rows)
__device__ __half g_qkv [BM*QKVS];          // fused QKV fp16 (ORIGINAL rows)
__device__ int    g_rowmap[BM];             // compact -> orig
__device__ int    g_o2c  [BM];              // orig -> compact (0 if masked)
__device__ int    g_cnt;                    // compact row count Mc

// ---------------- helpers ---------------------------------------------------
__device__ __forceinline__ uint32_t smem_u32(const void* p) {
    uint32_t a;
    asm("{ .reg .u64 t; cvta.to.shared.u64 t, %1; cvt.u32.u64 %0, t; }"
        : "=r"(a) : "l"(p));
    return a;
}
#define MMAH(d, a, b) \
    asm volatile( \
        "mma.sync.aligned.m16n8k16.row.col.f32.f16.f16.f32 " \
        "{%0,%1,%2,%3}, {%4,%5,%6,%7}, {%8,%9}, {%0,%1,%2,%3};" \
        : "+f"((d)[0]), "+f"((d)[1]), "+f"((d)[2]), "+f"((d)[3]) \
        : "r"((a)[0]), "r"((a)[1]), "r"((a)[2]), "r"((a)[3]), \
          "r"((b)[0]), "r"((b)[1]))
#define LDMX4(r, addr) \
    asm volatile("ldmatrix.sync.aligned.m8n8.x4.shared.b16 {%0,%1,%2,%3}, [%4];" \
        : "=r"((r)[0]), "=r"((r)[1]), "=r"((r)[2]), "=r"((r)[3]) : "r"(addr))
#define CPASYNC16(smaddr, gptr) \
    asm volatile("cp.async.cg.shared.global [%0], [%1], 16;" \
        :: "r"(smaddr), "l"(gptr))
#define CPCOMMIT() asm volatile("cp.async.commit_group;")
#define CPWAIT(n)  asm volatile("cp.async.wait_group %0;" :: "n"(n))

__device__ __forceinline__ uint32_t packh2(float a, float b) {
    __half2 h = __floats2half2_rn(a, b);
    return *(uint32_t*)&h;
}

// ---------------------------------------------------------------------------
// Mega-prep: one launch fusing all independent prologue work.
// Roles by blockIdx.x (256 threads each):
//   [0, 8192)                cvt H (unmasked rows only)
//   [8192, 12288)            cvt 4 weights
//   [12288, 20480)           zero masked rows of out
//   [20480, 24576)           zero V-third of masked qkv rows
//   24576                    mask scan + rowmap/o2c/cnt + bias concat
// ---------------------------------------------------------------------------
#define NB_CVTH 8192
#define NB_CVTW 4096
#define NB_ZERO 8192
#define NB_ZV   4096
#define NB_PREP (NB_CVTH + NB_CVTW + NB_ZERO + NB_ZV + 1)

__global__ void mega_prep(const float4* __restrict__ H,
                          const float4* __restrict__ w0, const float4* __restrict__ w1,
                          const float4* __restrict__ w2, const float4* __restrict__ w3,
                          const float* __restrict__ bq, const float* __restrict__ bk,
                          const float* __restrict__ bv,
                          const int* __restrict__ mask,
                          float4* __restrict__ out) {
    const int bid = blockIdx.x;
    const int tid = threadIdx.x;

    if (bid < NB_CVTH) {
        const int i = bid * 256 + tid;              // < 2M
        if (mask[i >> 8] <= 0) return;              // masked rows never gathered
        float4 v = H[i];
        __half2* Y = (__half2*)g_A;
        Y[2*i]   = __floats2half2_rn(v.x, v.y);
        Y[2*i+1] = __floats2half2_rn(v.z, v.w);
    } else if (bid < NB_CVTH + NB_CVTW) {
        const int r = bid - NB_CVTH;
        const int w = r >> 10;
        const int i = (r & 1023) * 256 + tid;
        const float4* src = (w == 0) ? w0 : (w == 1) ? w1 : (w == 2) ? w2 : w3;
        float4 v = src[i];
        __half2* Y = (__half2*)(g_W + (size_t)w * DMODEL * DMODEL);
        Y[2*i]   = __floats2half2_rn(v.x, v.y);
        Y[2*i+1] = __floats2half2_rn(v.z, v.w);
    } else if (bid < NB_CVTH + NB_CVTW + NB_ZERO) {
        const int i = (bid - NB_CVTH - NB_CVTW) * 256 + tid;
        if (mask[i >> 8] <= 0) out[i] = make_float4(0.f, 0.f, 0.f, 0.f);
    } else if (bid < NB_CVTH + NB_CVTW + NB_ZERO + NB_ZV) {
        // zero the V section (cols 2048..3071) of masked qkv rows:
        // garbage fp16 there could be inf/NaN; P=0 times NaN would poison P.V
        const int i = (bid - NB_CVTH - NB_CVTW - NB_ZERO) * 256 + tid;  // < 1M
        const int row = i >> 7;               // 128 uint4 per row V-section
        if (mask[row] > 0) return;
        const int c16 = i & 127;
        *(uint4*)(g_qkv + (size_t)row * QKVS + 2048 + c16 * 8) = make_uint4(0,0,0,0);
    } else {
        __shared__ int wsum[8];
        const int lane = tid & 31, wid = tid >> 5;
        const int base = tid * 32;
        uint32_t bits = 0;
#pragma unroll
        for (int e = 0; e < 32; e++)
            if (mask[base + e] > 0) bits |= (1u << e);
        const int tot = __popc(bits);
        int inc = tot;
#pragma unroll
        for (int d = 1; d < 32; d <<= 1) {
            int t = __shfl_up_sync(0xffffffffu, inc, d);
            if (lane >= d) inc += t;
        }
        if (lane == 31) wsum[wid] = inc;
        __syncthreads();
        if (tid < 8) {
            int s = wsum[tid];
#pragma unroll
            for (int d = 1; d < 8; d <<= 1) {
                int t = __shfl_up_sync(0xffu, s, d);
                if (tid >= d) s += t;
            }
            wsum[tid] = s;
        }
        __syncthreads();
        int excl = inc - tot + ((wid > 0) ? wsum[wid - 1] : 0);
#pragma unroll
        for (int e = 0; e < 32; e++) {
            if (bits & (1u << e)) { g_rowmap[excl] = base + e; g_o2c[base + e] = excl; excl++; }
            else g_o2c[base + e] = 0;
        }
        if (tid == 255) g_cnt = excl;
        for (int i = tid; i < DMODEL; i += 256) {
            g_bias[i]        = bq[i];
            g_bias[1024 + i] = bk[i];
            g_bias[2048 + i] = bv[i];
        }
    }
}

// ---------------------------------------------------------------------------
// fp16 GEMM (NT): C[m,n] = sum_k A[m,k]*B[n,k] + bias[n]
// Optional A-row gather (gmap), C-row scatter (smap), compact bound (cntp).
// 128x128 CTA tile, 256 thr, BK=64, 3-stage cp.async, 2 CTAs/SM,
// single barrier per k-iteration.
// ---------------------------------------------------------------------------
#define BK 64
#define ROWW 36
#define PIECE_W (128*ROWW)
#define STAGE_W (2*PIECE_W)
#define NSTAGE 3
#define GEMM_SMEM (NSTAGE*STAGE_W*4)      // 110592 bytes
#define NKT (DMODEL/BK)                   // 16

__global__ __launch_bounds__(256, 2)
void gemm_h(const __half* __restrict__ A, const __half* __restrict__ B,
            const float* __restrict__ bias, int ldc,
            float* __restrict__ Cf, __half* __restrict__ Ch,
            const int* __restrict__ gmap, const int* __restrict__ smap,
            const int* __restrict__ cntp) {
    const int m0 = blockIdx.y * 128, n0 = blockIdx.x * 128;
    const int Mc = cntp ? *cntp : (1 << 30);
    if (m0 >= Mc) return;

    extern __shared__ __align__(16) uint32_t smw[];
    const uint32_t smb = smem_u32(smw);

    const int tid = threadIdx.x;
    const int wid = tid >> 5, lid = tid & 31;
    const int wm = wid >> 2, wn = wid & 3;
    const int r4 = lid >> 2, c4 = lid & 3;
    const int m8 = lid >> 3, l8 = lid & 7;

    const int lrow = tid >> 3;
    const int lc   = tid & 7;
    const __half* gAj[4];
#pragma unroll
    for (int j = 0; j < 4; j++) {
        int rm = m0 + lrow + 32 * j;
        if (gmap) rm = gmap[rm];
        gAj[j] = A + (size_t)rm * DMODEL + lc * 8;
    }
    const __half* gB = B + (size_t)(n0 + lrow) * DMODEL + lc * 8;
    const uint32_t dw = (uint32_t)(lrow * ROWW + lc * 4);

    const uint32_t a_off = (uint32_t)((wm * 64 + (m8 & 1) * 8 + l8) * ROWW + (m8 >> 1) * 4);
    const uint32_t b_off = (uint32_t)((wn * 32 + (m8 >> 1) * 8 + l8) * ROWW + (m8 & 1) * 4);

    float acc[4][4][4];
#pragma unroll
    for (int a = 0; a < 4; a++)
#pragma unroll
        for (int b = 0; b < 4; b++)
#pragma unroll
            for (int c = 0; c < 4; c++) acc[a][b][c] = 0.f;

#pragma unroll
    for (int s = 0; s < NSTAGE - 1; s++) {
        const uint32_t sa = smb + (s * STAGE_W) * 4;
        const int ko = s * BK;
#pragma unroll
        for (int j = 0; j < 4; j++) {
            const uint32_t d = (dw + j * 32 * ROWW) * 4;
            CPASYNC16(sa + d,               gAj[j] + ko);
            CPASYNC16(sa + PIECE_W * 4 + d, gB + (size_t)j * 32 * DMODEL + ko);
        }
        CPCOMMIT();
    }

    for (int kt = 0; kt < NKT; kt++) {
        CPWAIT(NSTAGE - 2);
        __syncthreads();

        if (kt + NSTAGE - 1 < NKT) {
            const int s = (kt + NSTAGE - 1) % NSTAGE;
            const uint32_t sa = smb + (s * STAGE_W) * 4;
            const int ko = (kt + NSTAGE - 1) * BK;
#pragma unroll
            for (int j = 0; j < 4; j++) {
                const uint32_t d = (dw + j * 32 * ROWW) * 4;
                CPASYNC16(sa + d,               gAj[j] + ko);
                CPASYNC16(sa + PIECE_W * 4 + d, gB + (size_t)j * 32 * DMODEL + ko);
            }
        }
        CPCOMMIT();

        const uint32_t sA = smb + ((kt % NSTAGE) * STAGE_W) * 4;
        const uint32_t sB = sA + PIECE_W * 4;

#pragma unroll
        for (int ks = 0; ks < 4; ks++) {
            uint32_t af[4][4], bf[2][4];
#pragma unroll
            for (int mt = 0; mt < 4; mt++)
                LDMX4(af[mt], sA + (a_off + mt * 16 * ROWW + ks * 8) * 4);
#pragma unroll
            for (int ntp = 0; ntp < 2; ntp++)
                LDMX4(bf[ntp], sB + (b_off + ntp * 16 * ROWW + ks * 8) * 4);
#pragma unroll
            for (int mt = 0; mt < 4; mt++)
#pragma unroll
                for (int ntp = 0; ntp < 2; ntp++) {
                    MMAH(acc[mt][2 * ntp],     af[mt], &bf[ntp][0]);
                    MMAH(acc[mt][2 * ntp + 1], af[mt], &bf[ntp][2]);
                }
        }
    }

#pragma unroll
    for (int mt = 0; mt < 4; mt++) {
        const int ro0 = m0 + wm * 64 + mt * 16 + r4;
        const int ro1 = ro0 + 8;
        const bool w0 = ro0 < Mc, w1 = ro1 < Mc;
        const int so0 = (w0 && smap) ? smap[ro0] : ro0;
        const int so1 = (w1 && smap) ? smap[ro1] : ro1;
#pragma unroll
        for (int nt = 0; nt < 4; nt++) {
            const int col = n0 + wn * 32 + nt * 8 + c4 * 2;
            const float bx = bias[col], by = bias[col + 1];
            const float v0x = acc[mt][nt][0] + bx, v0y = acc[mt][nt][1] + by;
            const float v1x = acc[mt][nt][2] + bx, v1y = acc[mt][nt][3] + by;
            if (Cf) {
                if (w0) *(float2*)(Cf + (size_t)so0 * ldc + col) = make_float2(v0x, v0y);
                if (w1) *(float2*)(Cf + (size_t)so1 * ldc + col) = make_float2(v1x, v1y);
            } else {
                if (w0) *(uint32_t*)(Ch + (size_t)so0 * ldc + col) = packh2(v0x, v0y);
                if (w1) *(uint32_t*)(Ch + (size_t)so1 * ldc + col) = packh2(v1x, v1y);
            }
        }
    }
}

// ---------------------------------------------------------------------------
// fp16 HMMA banded attention, window +-16, DIRECT original-row QKV layout
// (no o2c indirection). Masked rows: K garbage is discarded via SELECT
// masking (score replaced by -1e9 entirely); V of masked rows is zeroed by
// mega_prep (0 * 0 = 0 in P.V); Q garbage only affects masked-query rows,
// which are never written. Key tile 96 rows [i0-16, i0+80); per-warp range
// [16w, 16w+48) = 3 key blocks. smem 27.6 KB, 5 CTAs/SM.
// ---------------------------------------------------------------------------
#define NKB 3
#define KEYR 96
#define AQW 36
#define AVW 52
#define OFF_K  0
#define OFF_VT (OFF_K + KEYR*AQW)        // 3456
#define OFF_BT (OFF_VT + 64*AVW)         // 6784
#define OFF_AD (OFF_BT + 32)             // 6816
#define ATTN_SMEM_W (OFF_AD + KEYR)      // 6912 words
#define ATTN_SMEM (ATTN_SMEM_W*4)        // 27648 bytes

__global__ __launch_bounds__(128, 5)
void attn_mma(const __half* __restrict__ qkv, __half* __restrict__ ao,
              const int* __restrict__ mask) {
    extern __shared__ __align__(16) uint32_t sw[];
    float* sf = (float*)sw;
    const uint32_t smb = smem_u32(sw);

    const int qt = blockIdx.x, h = blockIdx.y, b = blockIdx.z;
    const int i0 = qt * 64;
    const int j0 = i0 - 16;
    const int tid = threadIdx.x;
    const int w = tid >> 5, lane = tid & 31;
    const int r4 = lane >> 2, c4 = lane & 3;
    const int m8 = lane >> 3, l8 = lane & 7;
    const size_t tok0 = (size_t)b * SEQ + i0;
    const int hc = h * DHEAD;

    // ---- load K (96 rows, direct) ----
    for (int idx = tid; idx < KEYR * 8; idx += 128) {
        const int jj = idx >> 3, c8 = idx & 7;
        const int j = j0 + jj;
        uint4 v4 = make_uint4(0, 0, 0, 0);
        if (j >= 0 && j < SEQ)
            v4 = *(const uint4*)(qkv + ((size_t)b * SEQ + j) * QKVS + 1024 + hc + c8 * 8);
        *(uint4*)&sw[OFF_K + jj * AQW + c8 * 4] = v4;
    }
    // ---- load V transposed (direct): 48 word cols ----
#pragma unroll
    for (int d8i = 0; d8i < 2; d8i++) {
        const int d8 = w * 2 + d8i;
#pragma unroll
        for (int ch = 0; ch < 2; ch++) {
            const int jjp = ch * 32 + lane;
            if (jjp >= KEYR / 2) continue;
            const int ja = j0 + 2 * jjp, jb = ja + 1;
            uint4 a4 = make_uint4(0,0,0,0), b4 = make_uint4(0,0,0,0);
            if (ja >= 0 && ja < SEQ)
                a4 = *(const uint4*)(qkv + ((size_t)b * SEQ + ja) * QKVS + 2048 + hc + d8 * 8);
            if (jb >= 0 && jb < SEQ)
                b4 = *(const uint4*)(qkv + ((size_t)b * SEQ + jb) * QKVS + 2048 + hc + d8 * 8);
            const uint16_t* ua = (const uint16_t*)&a4;
            const uint16_t* ub = (const uint16_t*)&b4;
#pragma unroll
            for (int e = 0; e < 8; e++)
                sw[OFF_VT + (d8 * 8 + e) * AVW + jjp] = (uint32_t)ua[e] | ((uint32_t)ub[e] << 16);
        }
    }
    // ---- bias table (dist <= 31) + mask flag ----
    if (tid < 32)
        sf[OFF_BT + tid] = logf(expf(-(float)tid) + 1e-12f);
    for (int jj = tid; jj < KEYR; jj += 128) {
        const int j = j0 + jj;
        sf[OFF_AD + jj] = (j >= 0 && j < SEQ && mask[(size_t)b * SEQ + j] > 0) ? 0.f : -1e9f;
    }

    // ---- Q A-fragments loaded directly from gmem ----
    uint32_t qa[4][4];
    {
        const size_t rowA = (tok0 + w * 16 + r4) * QKVS + hc;
        const size_t rowB = (tok0 + w * 16 + r4 + 8) * QKVS + hc;
#pragma unroll
        for (int ks = 0; ks < 4; ks++) {
            const int colA = ks * 16 + 2 * c4;
            qa[ks][0] = *(const uint32_t*)(qkv + rowA + colA);
            qa[ks][1] = *(const uint32_t*)(qkv + rowB + colA);
            qa[ks][2] = *(const uint32_t*)(qkv + rowA + colA + 8);
            qa[ks][3] = *(const uint32_t*)(qkv + rowB + colA + 8);
        }
    }
    __syncthreads();

    // ---- S = Q K^T over per-warp key range [16w, 16w+48) ----
    const uint32_t koff = (uint32_t)(((m8 >> 1) * 8 + l8) * AQW + (m8 & 1) * 4);
    float s[2 * NKB][4];
#pragma unroll
    for (int ntp = 0; ntp < NKB; ntp++) {
        float* s0 = s[2 * ntp];
        float* s1 = s[2 * ntp + 1];
#pragma unroll
        for (int e = 0; e < 4; e++) { s0[e] = 0.f; s1[e] = 0.f; }
        const uint32_t krow = (uint32_t)((16 * w + 16 * ntp) * AQW);
#pragma unroll
        for (int ks = 0; ks < 4; ks++) {
            uint32_t kf[4];
            LDMX4(kf, smb + (OFF_K + krow + koff + ks * 8) * 4);
            MMAH(s0, qa[ks], &kf[0]);
            MMAH(s1, qa[ks], &kf[2]);
        }
    }

    // ---- bias + SELECT mask (kills garbage-K scores entirely), softmax ----
    float mlo = -1e30f, mhi = -1e30f;
#pragma unroll
    for (int nt = 0; nt < 2 * NKB; nt++) {
#pragma unroll
        for (int e = 0; e < 4; e++) {
            const int jj = 16 * w + nt * 8 + 2 * c4 + (e & 1);
            const int rowq = w * 16 + r4 + (e >> 1) * 8;
            int dist = rowq + 16 - jj; dist = dist < 0 ? -dist : dist;
            const float adv = sf[OFF_AD + jj];
            float v = s[nt][e] * 0.125f + sf[OFF_BT + dist];
            v = (adv < -1.f) ? -1e9f : v;      // select, NOT add: robust to NaN
            s[nt][e] = v;
            if (e < 2) mlo = fmaxf(mlo, v); else mhi = fmaxf(mhi, v);
        }
    }
    mlo = fmaxf(mlo, __shfl_xor_sync(0xffffffff, mlo, 1));
    mlo = fmaxf(mlo, __shfl_xor_sync(0xffffffff, mlo, 2));
    mhi = fmaxf(mhi, __shfl_xor_sync(0xffffffff, mhi, 1));
    mhi = fmaxf(mhi, __shfl_xor_sync(0xffffffff, mhi, 2));

    float llo = 0.f, lhi = 0.f;
#pragma unroll
    for (int nt = 0; nt < 2 * NKB; nt++) {
#pragma unroll
        for (int e = 0; e < 4; e++) {
            const float p = __expf(s[nt][e] - ((e < 2) ? mlo : mhi));
            s[nt][e] = p;
            if (e < 2) llo += p; else lhi += p;
        }
    }
    llo += __shfl_xor_sync(0xffffffff, llo, 1);
    llo += __shfl_xor_sync(0xffffffff, llo, 2);
    lhi += __shfl_xor_sync(0xffffffff, lhi, 1);
    lhi += __shfl_xor_sync(0xffffffff, lhi, 2);

    // ---- pack P into fp16 A-fragments ----
    uint32_t pa[NKB][4];
#pragma unroll
    for (int kb = 0; kb < NKB; kb++) {
        pa[kb][0] = packh2(s[2*kb][0],   s[2*kb][1]);
        pa[kb][1] = packh2(s[2*kb][2],   s[2*kb][3]);
        pa[kb][2] = packh2(s[2*kb+1][0], s[2*kb+1][1]);
        pa[kb][3] = packh2(s[2*kb+1][2], s[2*kb+1][3]);
    }

    // ---- O = P V ----
    const uint32_t voff = (uint32_t)(((m8 >> 1) * 8 + l8) * AVW + (m8 & 1) * 4);
    float o[8][4];
#pragma unroll
    for (int dt = 0; dt < 8; dt++)
#pragma unroll
        for (int e = 0; e < 4; e++) o[dt][e] = 0.f;

#pragma unroll
    for (int kb = 0; kb < NKB; kb++) {
        const uint32_t kcol = (uint32_t)(8 * w + 8 * kb);
#pragma unroll
        for (int dtp = 0; dtp < 4; dtp++) {
            uint32_t vf[4];
            LDMX4(vf, smb + (OFF_VT + voff + dtp * 16 * AVW + kcol) * 4);
            MMAH(o[2*dtp],     pa[kb], &vf[0]);
            MMAH(o[2*dtp + 1], pa[kb], &vf[2]);
        }
    }

    // ---- epilogue: normalize + write AO at ORIGINAL rows (unmasked only) ----
    const float invlo = (llo > 0.f) ? 1.f / llo : 0.f;
    const float invhi = (lhi > 0.f) ? 1.f / lhi : 0.f;
    const size_t olo = tok0 + w * 16 + r4;
    const size_t ohi = olo + 8;
    const bool wlo = mask[olo] > 0, whi = mask[ohi] > 0;
#pragma unroll
    for (int dt = 0; dt < 8; dt++) {
        const int col = hc + dt * 8 + 2 * c4;
        if (wlo) *(uint32_t*)(ao + olo * DMODEL + col) = packh2(o[dt][0] * invlo, o[dt][1] * invlo);
        if (whi) *(uint32_t*)(ao + ohi * DMODEL + col) = packh2(o[dt][2] * invhi, o[dt][3] * invhi);
    }
}

// ---------------------------------------------------------------------------
extern "C" void kernel_launch(void* const* d_in, const int* in_sizes, int n_in,
                              void* d_out, int out_size) {
    const float* H    = (const float*)d_in[0];
    const int*   pmsk = (const int*)  d_in[1];
    const float* Wq   = (const float*)d_in[2];
    const float* bq   = (const float*)d_in[3];
    const float* Wk   = (const float*)d_in[4];
    const float* bk   = (const float*)d_in[5];
    const float* Wv   = (const float*)d_in[6];
    const float* bv   = (const float*)d_in[7];
    const float* Wo   = (const float*)d_in[8];
    const float* bo   = (const float*)d_in[9];
    float* out = (float*)d_out;

    void *pA, *pW, *pB, *pAO, *pqkv, *pmap, *pcnt;
    cudaGetSymbolAddress(&pA,   g_A);
    cudaGetSymbolAddress(&pW,   g_W);
    cudaGetSymbolAddress(&pB,   g_bias);
    cudaGetSymbolAddress(&pAO,  g_AO);
    cudaGetSymbolAddress(&pqkv, g_qkv);
    cudaGetSymbolAddress(&pmap, g_rowmap);
    cudaGetSymbolAddress(&pcnt, g_cnt);

    __half* Ah = (__half*)pA;
    __half* Wh = (__half*)pW;
    float*  br = (float*)pB;
    const int* rowmap = (const int*)pmap;
    const int* cnt    = (const int*)pcnt;

    cudaFuncSetAttribute(gemm_h,   cudaFuncAttributeMaxDynamicSharedMemorySize, GEMM_SMEM);
    cudaFuncSetAttribute(attn_mma, cudaFuncAttributeMaxDynamicSharedMemorySize, ATTN_SMEM);

    // fused prologue (conversions + scan + bias concat + zero-outs)
    mega_prep<<<NB_PREP, 256>>>((const float4*)H,
                                (const float4*)Wq, (const float4*)Wk,
                                (const float4*)Wv, (const float4*)Wo,
                                bq, bk, bv, pmsk, (float4*)out);

    // fused QKV GEMM on compact rows, SCATTER to original rows
    dim3 gqkv(QKVS / 128, BM / 128);   // (24, 64); CTAs beyond Mc exit
    gemm_h<<<gqkv, 256, GEMM_SMEM>>>(Ah, Wh, br, QKVS, nullptr,
                                     (__half*)pqkv, rowmap, rowmap, cnt);

    // attention: direct original-row layout, no indirection
    dim3 ga(SEQ / 64, NHEAD, BATCH);
    attn_mma<<<ga, 128, ATTN_SMEM>>>((const __half*)pqkv, (__half*)pAO, pmsk);

    // output projection: gather AO rows via rowmap, scatter out via rowmap
    dim3 go(DMODEL / 128, BM / 128);
    gemm_h<<<go, 256, GEMM_SMEM>>>((const __half*)pAO, Wh + 3ul*DMODEL*DMODEL, bo,
                                   DMODEL, out, nullptr, rowmap, rowmap, cnt);
}